// round 13
// baseline (speedup 1.0000x reference)
#include <cuda_runtime.h>
#include <cuda_bf16.h>
#include <stdint.h>
#include <stddef.h>

#define T_STEPS 200
#define NTHR 512

// ---------------- smem layout (byte offsets) ----------------
#define A0B    0          // weight image slot 0 (69632 B: hi plane 34816 + lo plane)
#define A1B    69632      // slot 1
#define XHhiB  139264     // h   B-tile hi [32][136] bf16 (8704 B); lo at +8704
#define XHloB  147968
#define XRhiB  156672     // r*h B-tile
#define XRloB  165376
#define XGhiB  174080     // gru x B-tile [32][56] bf16 (3584 B); lo at +3584
#define XGloB  177664
// ---- float offsets ----
#define HMf    45312      // h fp32 master [32][132]  (4224 f)
#define DECf   49536      // dec weights [k=128][33]  (4224 f)
#define FBf    53760      // flow biases [l*512 + gate*128 + n] (1024 f)
#define WTf    54784      // flow t-row weights [l*384 + gate*128 + n] (768 f)
#define GBf    55552      // gru biases: br,bz,bin,bhn (512 f)
#define DBf    56064      // dec bias (32 f)
#define TVf    56096      // t values (32 f)
#define SMEM_BYTES 224512

__device__ __align__(16) unsigned short g_wimg[356352];   // 712704 B

__constant__ int c_stageImg[12] = {1,2,3,4,5,6,9,7,10,8,11,0};
__constant__ int c_imgOff[12]   = {0,69632,139264,208896,278528,348160,
                                   417792,487424,557056,626688,655360,684032};
__constant__ int c_imgSz[12]    = {69632,69632,69632,69632,69632,69632,
                                   69632,69632,69632,28672,28672,28672};

__device__ __forceinline__ float tanha(float x) {
    float y; asm("tanh.approx.f32 %0,%1;" : "=f"(y) : "f"(x)); return y;
}
__device__ __forceinline__ float siga(float x) { return fmaf(0.5f, tanha(0.5f * x), 0.5f); }

__device__ __forceinline__ void cpa16c(char* dst, const char* src) {
    unsigned d = (unsigned)__cvta_generic_to_shared(dst);
    asm volatile("cp.async.cg.shared.global [%0], [%1], 16;" :: "r"(d), "l"(src));
}
#define CP_COMMIT() asm volatile("cp.async.commit_group;" ::: "memory")
#define CP_WAIT0()  asm volatile("cp.async.wait_group 0;" ::: "memory")

__device__ __forceinline__ void ldm4(uint32_t& r0, uint32_t& r1, uint32_t& r2, uint32_t& r3, uint32_t a) {
    asm volatile("ldmatrix.sync.aligned.m8n8.x4.shared.b16 {%0,%1,%2,%3},[%4];"
        : "=r"(r0), "=r"(r1), "=r"(r2), "=r"(r3) : "r"(a));
}
__device__ __forceinline__ void mmabf(float* d, uint32_t a0, uint32_t a1, uint32_t a2, uint32_t a3,
                                      uint32_t b0, uint32_t b1) {
    asm volatile("mma.sync.aligned.m16n8k16.row.col.f32.bf16.bf16.f32 "
        "{%0,%1,%2,%3},{%4,%5,%6,%7},{%8,%9},{%0,%1,%2,%3};"
        : "+f"(d[0]), "+f"(d[1]), "+f"(d[2]), "+f"(d[3])
        : "r"(a0), "r"(a1), "r"(a2), "r"(a3), "r"(b0), "r"(b1));
}

// hi/lo bf16 store helpers
__device__ __forceinline__ void st_hl(char* smc, int hiB, int loB, int b, int k, float v) {
    __nv_bfloat16 h = __float2bfloat16(v);
    __nv_bfloat16 l = __float2bfloat16(v - __bfloat162float(h));
    const int e = (b * 136 + k) * 2;
    *(__nv_bfloat16*)(smc + hiB + e) = h;
    *(__nv_bfloat16*)(smc + loB + e) = l;
}
__device__ __forceinline__ void st_hl56(char* smc, int hiB, int loB, int b, int k, float v) {
    __nv_bfloat16 h = __float2bfloat16(v);
    __nv_bfloat16 l = __float2bfloat16(v - __bfloat162float(h));
    const int e = (b * 56 + k) * 2;
    *(__nv_bfloat16*)(smc + hiB + e) = h;
    *(__nv_bfloat16*)(smc + loB + e) = l;
}

// one matvec pass (split-N): this warp computes 2 n-tiles (nt = 2*nh + {0,1}).
// acc[4*j + f] = (m-tile, n-tile 2nh+j) fragment f.
// Bm4: base addr for merged hi/lo ldm4 (lanes 16-31 -> lo plane).
__device__ __forceinline__ void mma_pass(uint32_t Aaddr, int planeA,
                                         uint32_t Bm4, int nh,
                                         int strideX, int ksteps, float acc[8])
{
#pragma unroll 2
    for (int ks = 0; ks < ksteps; ks++) {
        uint32_t ah0, ah1, ah2, ah3, al0, al1, al2, al3;
        const uint32_t ab = Aaddr + ks * 32;
        ldm4(ah0, ah1, ah2, ah3, ab);
        ldm4(al0, al1, al2, al3, ab + planeA);
#pragma unroll
        for (int j = 0; j < 2; j++) {
            const int nt = 2 * nh + j;
            uint32_t bh0, bh1, bl0, bl1;
            ldm4(bh0, bh1, bl0, bl1, Bm4 + ks * 32 + nt * 8 * strideX);
            mmabf(acc + 4 * j, ah0, ah1, ah2, ah3, bh0, bh1);
            mmabf(acc + 4 * j, ah0, ah1, ah2, ah3, bl0, bl1);
            mmabf(acc + 4 * j, al0, al1, al2, al3, bh0, bh1);
        }
    }
}

// -------------------- prep: build bf16 hi/lo weight images --------------------
__global__ void prep_kernel(const float* fWr, const float* fWz, const float* fWh,
                            const float* Whh, const float* Wih)
{
    const int img = blockIdx.x, tid = threadIdx.x;
    if (img < 9) {
        unsigned short* dst = g_wimg + img * 34816;        // hi plane; lo at +17408
        for (int i = tid; i < 128 * 136; i += 256) {
            const int n = i / 136, k = i - n * 136;
            float v = 0.0f;
            if (k < 128) {
                if (img < 6) {
                    const int l = img / 3, g = img % 3;
                    const float* W = (g == 0 ? fWr : (g == 1 ? fWz : fWh)) + (size_t)l * 129 * 128;
                    v = W[k * 128 + n];
                } else {
                    v = Whh[(size_t)(img - 6) * 16384 + n * 128 + k];
                }
            }
            __nv_bfloat16 h = __float2bfloat16(v);
            __nv_bfloat16 l = __float2bfloat16(v - __bfloat162float(h));
            dst[n * 136 + k]         = *reinterpret_cast<unsigned short*>(&h);
            dst[17408 + n * 136 + k] = *reinterpret_cast<unsigned short*>(&l);
        }
    } else {
        const int g = img - 9;
        unsigned short* dst = g_wimg + 313344 + g * 14336; // hi plane; lo at +7168
        for (int i = tid; i < 128 * 56; i += 256) {
            const int n = i / 56, k = i - n * 56;
            const float v = (k < 40) ? Wih[(size_t)(g * 128 + n) * 40 + k] : 0.0f;
            __nv_bfloat16 h = __float2bfloat16(v);
            __nv_bfloat16 l = __float2bfloat16(v - __bfloat162float(h));
            dst[n * 56 + k]        = *reinterpret_cast<unsigned short*>(&h);
            dst[7168 + n * 56 + k] = *reinterpret_cast<unsigned short*>(&l);
        }
    }
}

__device__ __forceinline__ void phsync(int p, char* smc, int tid) {
    CP_WAIT0(); __syncthreads();
    const int img = c_stageImg[p];
    char* dst = smc + ((p & 1) ? A0B : A1B);
    const char* src = (const char*)g_wimg + c_imgOff[img];
    const int n = c_imgSz[img] >> 4;
    for (int i = tid; i < n; i += NTHR) cpa16c(dst + i * 16, src + i * 16);
    CP_COMMIT();
}

#define ZACC() do { _Pragma("unroll") for (int q = 0; q < 8; q++) acc[q] = 0.0f; } while (0)
#define CURS(p) (sb + (((p) & 1) ? A1B : A0B))

__global__ void __launch_bounds__(NTHR, 1)
odernn_mma(const float* __restrict__ s, const float* __restrict__ a, const float* __restrict__ t,
           const float* __restrict__ fWr, const float* __restrict__ fbr,
           const float* __restrict__ fWz, const float* __restrict__ fbz,
           const float* __restrict__ fWh, const float* __restrict__ fbh,
           const float* __restrict__ ftw,
           const float* __restrict__ bih, const float* __restrict__ bhh,
           const float* __restrict__ decW, const float* __restrict__ decb,
           float* __restrict__ outs, float* __restrict__ hids)
{
    extern __shared__ char smc[];
    float* smf = (float*)smc;
    const int tid = threadIdx.x;
    const int row0 = blockIdx.x * 32;
    const uint32_t sb = (uint32_t)__cvta_generic_to_shared(smc);

    const int w = tid >> 5, lane = tid & 31;
    const int mw = w & 7, nh = w >> 3;       // m-tile 0..7, n-half 0..1
    const int g = lane >> 2, tg = lane & 3;
    const int og = 16 * mw + g, og8 = og + 8;
    // ldmatrix lane offsets
    const int arow = (lane & 7) + ((lane >> 3) & 1) * 8;
    const int acolh = (lane >> 4) * 16;
    const uint32_t aoffB = (uint32_t)((16 * mw + arow) * 272 + acolh);
    const uint32_t aoffG = (uint32_t)((16 * mw + arow) * 112 + acolh);
    // merged hi/lo B offsets: lanes 16-31 address the lo plane
    const uint32_t boffB4 = (uint32_t)((lane & 7) * 272 + ((lane >> 3) & 1) * 16 + (lane >> 4) * 8704);
    const uint32_t boffG4 = (uint32_t)((lane & 7) * 112 + ((lane >> 3) & 1) * 16 + (lane >> 4) * 3584);

    // ---- one-time init ----
    for (int i = tid; i < 10496; i += NTHR) smf[34816 + i] = 0.0f;   // XH/XR/XG hi+lo zero
    for (int i = tid; i < 4224; i += NTHR) smf[HMf + i] = 0.0f;      // h master zero
    for (int i = tid; i < 4096; i += NTHR) {                          // dec [k][33]
        const int d = i >> 7, k = i & 127;
        smf[DECf + k * 33 + d] = decW[i];
    }
    if (tid < 128) {
#pragma unroll
        for (int l = 0; l < 2; l++) {
            smf[FBf + l * 512 +   0 + tid] = fbr[l * 128 + tid];
            smf[FBf + l * 512 + 128 + tid] = fbz[l * 128 + tid];
            smf[FBf + l * 512 + 256 + tid] = fbh[l * 128 + tid];
            smf[FBf + l * 512 + 384 + tid] = ftw[l * 128 + tid];
            smf[WTf + l * 384 +   0 + tid] = fWr[l * 16512 + 16384 + tid];
            smf[WTf + l * 384 + 128 + tid] = fWz[l * 16512 + 16384 + tid];
            smf[WTf + l * 384 + 256 + tid] = fWh[l * 16512 + 16384 + tid];
        }
        smf[GBf +   0 + tid] = bih[tid] + bhh[tid];
        smf[GBf + 128 + tid] = bih[128 + tid] + bhh[128 + tid];
        smf[GBf + 256 + tid] = bih[256 + tid];
        smf[GBf + 384 + tid] = bhh[256 + tid];
    }
    if (tid < 32) smf[DBf + tid] = decb[tid];
    __syncthreads();

    // prologue: stage img0 -> slot0
    {
        const char* src = (const char*)g_wimg;
        for (int i = tid; i < (69632 >> 4); i += NTHR) cpa16c(smc + A0B + i * 16, src + i * 16);
        CP_COMMIT();
    }

#pragma unroll 1
    for (int ti = 0; ti < T_STEPS; ti++) {
        if (tid < 32) smf[TVf + tid] = t[(size_t)(row0 + tid) * T_STEPS + ti];
        for (int i = tid; i < 1280; i += NTHR) {
            const int b = i / 40, c = i - b * 40;
            const float v = (c < 32) ? s[((size_t)(row0 + b) * T_STEPS + ti) * 32 + c]
                                     : a[((size_t)(row0 + b) * T_STEPS + ti) * 8 + (c - 32)];
            st_hl56(smc, XGhiB, XGloB, b, c, v);
        }

        float acc[8], zf[8], rv[8];

        // =================== flow layers ===================
#pragma unroll 1
        for (int l = 0; l < 2; l++) {
            const int pb = l * 3;

            // ---- pass r ----
            phsync(pb + 0, smc, tid);
            ZACC();
            mma_pass(CURS(pb + 0) + aoffB, 34816, sb + XHhiB + boffB4, nh, 272, 8, acc);
            {
                const float wtA = smf[WTf + l * 384 + og],  wtB = smf[WTf + l * 384 + og8];
                const float brA = smf[FBf + l * 512 + og],  brB = smf[FBf + l * 512 + og8];
#pragma unroll
                for (int j = 0; j < 2; j++) {
                    const int b0 = 8 * (2 * nh + j) + 2 * tg;
                    const float tv0 = smf[TVf + b0], tv1 = smf[TVf + b0 + 1];
                    float r0 = 0.8f * siga(acc[4 * j + 0] + wtA * tv0 + brA);
                    float r1 = 0.8f * siga(acc[4 * j + 1] + wtA * tv1 + brA);
                    float r2 = 0.8f * siga(acc[4 * j + 2] + wtB * tv0 + brB);
                    float r3 = 0.8f * siga(acc[4 * j + 3] + wtB * tv1 + brB);
                    st_hl(smc, XRhiB, XRloB, b0,     og,  r0 * smf[HMf + b0 * 132 + og]);
                    st_hl(smc, XRhiB, XRloB, b0 + 1, og,  r1 * smf[HMf + (b0 + 1) * 132 + og]);
                    st_hl(smc, XRhiB, XRloB, b0,     og8, r2 * smf[HMf + b0 * 132 + og8]);
                    st_hl(smc, XRhiB, XRloB, b0 + 1, og8, r3 * smf[HMf + (b0 + 1) * 132 + og8]);
                }
            }

            // ---- pass z ----
            phsync(pb + 1, smc, tid);
            ZACC();
            mma_pass(CURS(pb + 1) + aoffB, 34816, sb + XHhiB + boffB4, nh, 272, 8, acc);
            {
                const float wtA = smf[WTf + l * 384 + 128 + og],  wtB = smf[WTf + l * 384 + 128 + og8];
                const float bzA = smf[FBf + l * 512 + 128 + og],  bzB = smf[FBf + l * 512 + 128 + og8];
#pragma unroll
                for (int j = 0; j < 2; j++) {
                    const int b0 = 8 * (2 * nh + j) + 2 * tg;
                    const float tv0 = smf[TVf + b0], tv1 = smf[TVf + b0 + 1];
                    zf[4 * j + 0] = 0.4f * siga(acc[4 * j + 0] + wtA * tv0 + bzA);
                    zf[4 * j + 1] = 0.4f * siga(acc[4 * j + 1] + wtA * tv1 + bzA);
                    zf[4 * j + 2] = 0.4f * siga(acc[4 * j + 2] + wtB * tv0 + bzB);
                    zf[4 * j + 3] = 0.4f * siga(acc[4 * j + 3] + wtB * tv1 + bzB);
                }
            }

            // ---- pass u + combine ----
            phsync(pb + 2, smc, tid);
            ZACC();
            mma_pass(CURS(pb + 2) + aoffB, 34816, sb + XRhiB + boffB4, nh, 272, 8, acc);
            {
                const float wtA = smf[WTf + l * 384 + 256 + og],  wtB = smf[WTf + l * 384 + 256 + og8];
                const float bhA = smf[FBf + l * 512 + 256 + og],  bhB = smf[FBf + l * 512 + 256 + og8];
                const float twA = smf[FBf + l * 512 + 384 + og],  twB = smf[FBf + l * 512 + 384 + og8];
#define FLOWU(jj, bb, oo, wt, bh, tw, tvv) do { \
                    const float u_ = tanha(acc[jj] + (wt) * (tvv) + (bh)); \
                    const float phi_ = tanha((tw) * (tvv)); \
                    const float h_ = smf[HMf + (bb) * 132 + (oo)]; \
                    const float hn_ = h_ + phi_ * zf[jj] * (u_ - h_); \
                    smf[HMf + (bb) * 132 + (oo)] = hn_; \
                    st_hl(smc, XHhiB, XHloB, (bb), (oo), hn_); \
                    if (l == 1) hids[((size_t)(row0 + (bb)) * T_STEPS + ti) * 128 + (oo)] = hn_; \
                } while (0)
#pragma unroll
                for (int j = 0; j < 2; j++) {
                    const int b0 = 8 * (2 * nh + j) + 2 * tg;
                    const float tv0 = smf[TVf + b0], tv1 = smf[TVf + b0 + 1];
                    FLOWU(4 * j + 0, b0,     og,  wtA, bhA, twA, tv0);
                    FLOWU(4 * j + 1, b0 + 1, og,  wtA, bhA, twA, tv1);
                    FLOWU(4 * j + 2, b0,     og8, wtB, bhB, twB, tv0);
                    FLOWU(4 * j + 3, b0 + 1, og8, wtB, bhB, twB, tv1);
                }
#undef FLOWU
            }
        }

        // =================== GRU ===================
        // r gate: gh_r then += gi_r
        phsync(6, smc, tid);
        ZACC();
        mma_pass(CURS(6) + aoffB, 34816, sb + XHhiB + boffB4, nh, 272, 8, acc);
        phsync(7, smc, tid);
        mma_pass(CURS(7) + aoffG, 14336, sb + XGhiB + boffG4, nh, 112, 3, acc);
        {
            const float bA = smf[GBf + og], bB = smf[GBf + og8];
#pragma unroll
            for (int j = 0; j < 2; j++) {
                rv[4 * j + 0] = siga(acc[4 * j + 0] + bA);
                rv[4 * j + 1] = siga(acc[4 * j + 1] + bA);
                rv[4 * j + 2] = siga(acc[4 * j + 2] + bB);
                rv[4 * j + 3] = siga(acc[4 * j + 3] + bB);
            }
        }
        // z gate
        phsync(8, smc, tid);
        ZACC();
        mma_pass(CURS(8) + aoffB, 34816, sb + XHhiB + boffB4, nh, 272, 8, acc);
        phsync(9, smc, tid);
        mma_pass(CURS(9) + aoffG, 14336, sb + XGhiB + boffG4, nh, 112, 3, acc);
        {
            const float bA = smf[GBf + 128 + og], bB = smf[GBf + 128 + og8];
#pragma unroll
            for (int j = 0; j < 2; j++) {
                zf[4 * j + 0] = siga(acc[4 * j + 0] + bA);
                zf[4 * j + 1] = siga(acc[4 * j + 1] + bA);
                zf[4 * j + 2] = siga(acc[4 * j + 2] + bB);
                zf[4 * j + 3] = siga(acc[4 * j + 3] + bB);
            }
        }
        // gh_n -> fold into rv
        phsync(10, smc, tid);
        ZACC();
        mma_pass(CURS(10) + aoffB, 34816, sb + XHhiB + boffB4, nh, 272, 8, acc);
        {
            const float bA = smf[GBf + 384 + og], bB = smf[GBf + 384 + og8];
#pragma unroll
            for (int j = 0; j < 2; j++) {
                rv[4 * j + 0] *= (acc[4 * j + 0] + bA);
                rv[4 * j + 1] *= (acc[4 * j + 1] + bA);
                rv[4 * j + 2] *= (acc[4 * j + 2] + bB);
                rv[4 * j + 3] *= (acc[4 * j + 3] + bB);
            }
        }
        // gi_n + combine
        phsync(11, smc, tid);
        ZACC();
        mma_pass(CURS(11) + aoffG, 14336, sb + XGhiB + boffG4, nh, 112, 3, acc);
        {
            const float bA = smf[GBf + 256 + og], bB = smf[GBf + 256 + og8];
#define GRUF(jj, bb, oo, bi) do { \
                const float nn_ = tanha(acc[jj] + (bi) + rv[jj]); \
                const float h_ = smf[HMf + (bb) * 132 + (oo)]; \
                const float hn_ = nn_ + zf[jj] * (h_ - nn_); \
                smf[HMf + (bb) * 132 + (oo)] = hn_; \
                st_hl(smc, XHhiB, XHloB, (bb), (oo), hn_); \
            } while (0)
#pragma unroll
            for (int j = 0; j < 2; j++) {
                const int b0 = 8 * (2 * nh + j) + 2 * tg;
                GRUF(4 * j + 0, b0,     og,  bA);
                GRUF(4 * j + 1, b0 + 1, og,  bA);
                GRUF(4 * j + 2, b0,     og8, bB);
                GRUF(4 * j + 3, b0 + 1, og8, bB);
            }
#undef GRUF
        }
        __syncthreads();   // HM complete for decoder

        // =================== decoder (fp32) ===================
        {
            const int d = lane;
            const int bq = w * 2;
            float o0, o1;
            o0 = o1 = smf[DBf + d];
#pragma unroll 2
            for (int k = 0; k < 128; k += 4) {
                const float w0 = smf[DECf + (k + 0) * 33 + d];
                const float w1 = smf[DECf + (k + 1) * 33 + d];
                const float w2 = smf[DECf + (k + 2) * 33 + d];
                const float w3 = smf[DECf + (k + 3) * 33 + d];
                float4 h0 = *(const float4*)&smf[HMf + (bq + 0) * 132 + k];
                float4 h1 = *(const float4*)&smf[HMf + (bq + 1) * 132 + k];
                o0 = fmaf(h0.x, w0, fmaf(h0.y, w1, fmaf(h0.z, w2, fmaf(h0.w, w3, o0))));
                o1 = fmaf(h1.x, w0, fmaf(h1.y, w1, fmaf(h1.z, w2, fmaf(h1.w, w3, o1))));
            }
            outs[((size_t)(row0 + bq + 0) * T_STEPS + ti) * 32 + d] = o0;
            outs[((size_t)(row0 + bq + 1) * T_STEPS + ti) * 32 + d] = o1;
        }
    }
}

extern "C" void kernel_launch(void* const* d_in, const int* in_sizes, int n_in,
                              void* d_out, int out_size)
{
    (void)in_sizes; (void)n_in; (void)out_size;
    const float* s    = (const float*)d_in[0];
    const float* a    = (const float*)d_in[1];
    const float* t    = (const float*)d_in[2];
    const float* fWr  = (const float*)d_in[3];
    const float* fbr  = (const float*)d_in[4];
    const float* fWz  = (const float*)d_in[5];
    const float* fbz  = (const float*)d_in[6];
    const float* fWh  = (const float*)d_in[7];
    const float* fbh  = (const float*)d_in[8];
    const float* ftw  = (const float*)d_in[9];
    const float* Wih  = (const float*)d_in[10];
    const float* Whh  = (const float*)d_in[11];
    const float* bih  = (const float*)d_in[12];
    const float* bhh  = (const float*)d_in[13];
    const float* decW = (const float*)d_in[14];
    const float* decb = (const float*)d_in[15];

    float* outs = (float*)d_out;
    float* hids = outs + (size_t)4096 * T_STEPS * 32;

    prep_kernel<<<12, 256>>>(fWr, fWz, fWh, Whh, Wih);

    cudaFuncSetAttribute(odernn_mma, cudaFuncAttributeMaxDynamicSharedMemorySize, SMEM_BYTES);
    odernn_mma<<<128, NTHR, SMEM_BYTES>>>(s, a, t, fWr, fbr, fWz, fbz, fWh, fbh, ftw,
                                          bih, bhh, decW, decb, outs, hids);
}

// round 14
// speedup vs baseline: 1.4988x; 1.4988x over previous
#include <cuda_runtime.h>
#include <cuda_fp16.h>
#include <stdint.h>
#include <stddef.h>

#define T_STEPS 200
#define NTHR 512

// ---------------- smem layout (byte offsets) ----------------
#define A0B    0          // weight image slot 0 (34816 B, fp16 single plane)
#define A1B    34816      // slot 1
#define XHB    69632      // h   B-tile [32][136] fp16 (8704 B)
#define XRB    78336      // r*h B-tile (8704 B)
#define XGB    87040      // gru x B-tile [32][56] fp16 (3584 B)
// ---- float offsets ----
#define HMf    22656      // h fp32 master [32][132]  (4224 f)
#define DECf   26880      // dec weights [k=128][33]  (4224 f)
#define FBf    31104      // flow biases [l*512 + gate*128 + n] (1024 f)
#define WTf    32128      // flow t-row weights [l*384 + gate*128 + n] (768 f)
#define GBf    32896      // gru biases: br,bz,bin,bhn (512 f)
#define DBf    33408      // dec bias (32 f)
#define TVf    33440      // t values (32 f)
#define SMEM_BYTES 133888

// fp16 weight images in gmem (built once per launch by prep_kernel)
__device__ __align__(16) unsigned short g_wimg[178176];   // 356352 B

// image staged during phase p (for phase p+1); byte offsets / sizes
__constant__ int c_stageImg[12] = {1,2,3,4,5,6,9,7,10,8,11,0};
__constant__ int c_imgOff[12]   = {0,34816,69632,104448,139264,174080,
                                   208896,243712,278528,313344,327680,342016};
__constant__ int c_imgSz[12]    = {34816,34816,34816,34816,34816,34816,
                                   34816,34816,34816,14336,14336,14336};

__device__ __forceinline__ float tanha(float x) {
    float y; asm("tanh.approx.f32 %0,%1;" : "=f"(y) : "f"(x)); return y;
}
__device__ __forceinline__ float siga(float x) { return fmaf(0.5f, tanha(0.5f * x), 0.5f); }

__device__ __forceinline__ void cpa16c(char* dst, const char* src) {
    unsigned d = (unsigned)__cvta_generic_to_shared(dst);
    asm volatile("cp.async.cg.shared.global [%0], [%1], 16;" :: "r"(d), "l"(src));
}
#define CP_COMMIT() asm volatile("cp.async.commit_group;" ::: "memory")
#define CP_WAIT0()  asm volatile("cp.async.wait_group 0;" ::: "memory")

__device__ __forceinline__ void ldm4(uint32_t& r0, uint32_t& r1, uint32_t& r2, uint32_t& r3, uint32_t a) {
    asm volatile("ldmatrix.sync.aligned.m8n8.x4.shared.b16 {%0,%1,%2,%3},[%4];"
        : "=r"(r0), "=r"(r1), "=r"(r2), "=r"(r3) : "r"(a));
}
__device__ __forceinline__ void mmaf16(float* d, uint32_t a0, uint32_t a1, uint32_t a2, uint32_t a3,
                                       uint32_t b0, uint32_t b1) {
    asm volatile("mma.sync.aligned.m16n8k16.row.col.f32.f16.f16.f32 "
        "{%0,%1,%2,%3},{%4,%5,%6,%7},{%8,%9},{%0,%1,%2,%3};"
        : "+f"(d[0]), "+f"(d[1]), "+f"(d[2]), "+f"(d[3])
        : "r"(a0), "r"(a1), "r"(a2), "r"(a3), "r"(b0), "r"(b1));
}

// fp16 B-tile store helpers
__device__ __forceinline__ void st_h(char* smc, int baseB, int b, int k, float v) {
    *(__half*)(smc + baseB + (b * 136 + k) * 2) = __float2half(v);
}
__device__ __forceinline__ void st_h56(char* smc, int baseB, int b, int k, float v) {
    *(__half*)(smc + baseB + (b * 56 + k) * 2) = __float2half(v);
}

// one matvec pass: warp covers 1 m-tile x 2 n-tiles; single fp16 plane; 1 mma per (ks, nt)
__device__ __forceinline__ void mma_pass(uint32_t Aaddr, uint32_t Baddr, int ksteps, float acc[8])
{
#pragma unroll
    for (int ks = 0; ks < 8; ks++) {
        if (ks >= ksteps) break;
        uint32_t a0, a1, a2, a3, b0, b1, b2, b3;
        ldm4(a0, a1, a2, a3, Aaddr + ks * 32);
        ldm4(b0, b1, b2, b3, Baddr + ks * 32);
        mmaf16(acc + 0, a0, a1, a2, a3, b0, b1);
        mmaf16(acc + 4, a0, a1, a2, a3, b2, b3);
    }
}

// -------------------- prep: build fp16 weight images --------------------
// imgs 0..5 flow (Wr0,Wz0,Wh0,Wr1,Wz1,Wh1) [n][k] 128x136; 6..8 Whh gates; 9..11 Wih gates 128x56
__global__ void prep_kernel(const float* fWr, const float* fWz, const float* fWh,
                            const float* Whh, const float* Wih)
{
    const int img = blockIdx.x, tid = threadIdx.x;
    if (img < 9) {
        unsigned short* dst = g_wimg + img * 17408;
        for (int i = tid; i < 128 * 136; i += 256) {
            const int n = i / 136, k = i - n * 136;
            float v = 0.0f;
            if (k < 128) {
                if (img < 6) {
                    const int l = img / 3, g = img % 3;
                    const float* W = (g == 0 ? fWr : (g == 1 ? fWz : fWh)) + (size_t)l * 129 * 128;
                    v = W[k * 128 + n];
                } else {
                    v = Whh[(size_t)(img - 6) * 16384 + n * 128 + k];
                }
            }
            __half h = __float2half(v);
            dst[n * 136 + k] = *reinterpret_cast<unsigned short*>(&h);
        }
    } else {
        const int g = img - 9;
        unsigned short* dst = g_wimg + 156672 + g * 7168;
        for (int i = tid; i < 128 * 56; i += 256) {
            const int n = i / 56, k = i - n * 56;
            const float v = (k < 40) ? Wih[(size_t)(g * 128 + n) * 40 + k] : 0.0f;
            __half h = __float2half(v);
            dst[n * 56 + k] = *reinterpret_cast<unsigned short*>(&h);
        }
    }
}

__device__ __forceinline__ void phsync(int p, char* smc, int tid) {
    CP_WAIT0(); __syncthreads();
    const int img = c_stageImg[p];
    char* dst = smc + ((p & 1) ? A0B : A1B);
    const char* src = (const char*)g_wimg + c_imgOff[img];
    const int n = c_imgSz[img] >> 4;
    for (int i = tid; i < n; i += NTHR) cpa16c(dst + i * 16, src + i * 16);
    CP_COMMIT();
}

#define ZACC() do { _Pragma("unroll") for (int q = 0; q < 8; q++) acc[q] = 0.0f; } while (0)
#define CURS(p) (sb + (((p) & 1) ? A1B : A0B))

__global__ void __launch_bounds__(NTHR, 1)
odernn_mma(const float* __restrict__ s, const float* __restrict__ a, const float* __restrict__ t,
           const float* __restrict__ fWr, const float* __restrict__ fbr,
           const float* __restrict__ fWz, const float* __restrict__ fbz,
           const float* __restrict__ fWh, const float* __restrict__ fbh,
           const float* __restrict__ ftw,
           const float* __restrict__ bih, const float* __restrict__ bhh,
           const float* __restrict__ decW, const float* __restrict__ decb,
           float* __restrict__ outs, float* __restrict__ hids)
{
    extern __shared__ char smc[];
    float* smf = (float*)smc;
    const int tid = threadIdx.x;
    const int row0 = blockIdx.x * 32;
    const uint32_t sb = (uint32_t)__cvta_generic_to_shared(smc);

    const int w = tid >> 5, lane = tid & 31;
    const int mw = w & 7, nh = w >> 3;       // m-tile 0..7, n-half 0..1
    const int g = lane >> 2, tg = lane & 3;
    const int og = 16 * mw + g, og8 = og + 8;
    // A ldmatrix lane offsets (m16k16, 4 8x8 tiles)
    const uint32_t aoffB = (uint32_t)((16 * mw + (lane & 15)) * 272 + (lane >> 4) * 16);
    const uint32_t aoffG = (uint32_t)((16 * mw + (lane & 15)) * 112 + (lane >> 4) * 16);
    // B ldmatrix x4 covering two n-tiles (rows 16nh..16nh+15), k16
    const int brow = 16 * nh + (lane & 7) + ((lane >> 4) & 1) * 8;
    const uint32_t boffB = (uint32_t)(brow * 272 + ((lane >> 3) & 1) * 16);
    const uint32_t boffG = (uint32_t)(brow * 112 + ((lane >> 3) & 1) * 16);

    // ---- one-time init ----
    for (int i = tid; i < 5248; i += NTHR) smf[17408 + i] = 0.0f;    // XH/XR/XG zero
    for (int i = tid; i < 4224; i += NTHR) smf[HMf + i] = 0.0f;      // h master zero
    for (int i = tid; i < 4096; i += NTHR) {                          // dec [k][33]
        const int d = i >> 7, k = i & 127;
        smf[DECf + k * 33 + d] = decW[i];
    }
    if (tid < 128) {
#pragma unroll
        for (int l = 0; l < 2; l++) {
            smf[FBf + l * 512 +   0 + tid] = fbr[l * 128 + tid];
            smf[FBf + l * 512 + 128 + tid] = fbz[l * 128 + tid];
            smf[FBf + l * 512 + 256 + tid] = fbh[l * 128 + tid];
            smf[FBf + l * 512 + 384 + tid] = ftw[l * 128 + tid];
            smf[WTf + l * 384 +   0 + tid] = fWr[l * 16512 + 16384 + tid];
            smf[WTf + l * 384 + 128 + tid] = fWz[l * 16512 + 16384 + tid];
            smf[WTf + l * 384 + 256 + tid] = fWh[l * 16512 + 16384 + tid];
        }
        smf[GBf +   0 + tid] = bih[tid] + bhh[tid];
        smf[GBf + 128 + tid] = bih[128 + tid] + bhh[128 + tid];
        smf[GBf + 256 + tid] = bih[256 + tid];
        smf[GBf + 384 + tid] = bhh[256 + tid];
    }
    if (tid < 32) smf[DBf + tid] = decb[tid];
    __syncthreads();

    // prologue: stage img0 -> slot0
    {
        const char* src = (const char*)g_wimg;
        for (int i = tid; i < (34816 >> 4); i += NTHR) cpa16c(smc + A0B + i * 16, src + i * 16);
        CP_COMMIT();
    }

#pragma unroll 1
    for (int ti = 0; ti < T_STEPS; ti++) {
        if (tid < 32) smf[TVf + tid] = t[(size_t)(row0 + tid) * T_STEPS + ti];
        for (int i = tid; i < 1280; i += NTHR) {
            const int b = i / 40, c = i - b * 40;
            const float v = (c < 32) ? s[((size_t)(row0 + b) * T_STEPS + ti) * 32 + c]
                                     : a[((size_t)(row0 + b) * T_STEPS + ti) * 8 + (c - 32)];
            st_h56(smc, XGB, b, c, v);
        }

        float acc[8], zf[8], rv[8];

        // =================== flow layers ===================
#pragma unroll 1
        for (int l = 0; l < 2; l++) {
            const int pb = l * 3;

            // ---- pass r ----
            phsync(pb + 0, smc, tid);
            ZACC();
            mma_pass(CURS(pb + 0) + aoffB, sb + XHB + boffB, 8, acc);
            {
                const float wtA = smf[WTf + l * 384 + og],  wtB = smf[WTf + l * 384 + og8];
                const float brA = smf[FBf + l * 512 + og],  brB = smf[FBf + l * 512 + og8];
#pragma unroll
                for (int j = 0; j < 2; j++) {
                    const int b0 = 8 * (2 * nh + j) + 2 * tg;
                    const float tv0 = smf[TVf + b0], tv1 = smf[TVf + b0 + 1];
                    float r0 = 0.8f * siga(acc[4 * j + 0] + wtA * tv0 + brA);
                    float r1 = 0.8f * siga(acc[4 * j + 1] + wtA * tv1 + brA);
                    float r2 = 0.8f * siga(acc[4 * j + 2] + wtB * tv0 + brB);
                    float r3 = 0.8f * siga(acc[4 * j + 3] + wtB * tv1 + brB);
                    st_h(smc, XRB, b0,     og,  r0 * smf[HMf + b0 * 132 + og]);
                    st_h(smc, XRB, b0 + 1, og,  r1 * smf[HMf + (b0 + 1) * 132 + og]);
                    st_h(smc, XRB, b0,     og8, r2 * smf[HMf + b0 * 132 + og8]);
                    st_h(smc, XRB, b0 + 1, og8, r3 * smf[HMf + (b0 + 1) * 132 + og8]);
                }
            }

            // ---- pass z ----
            phsync(pb + 1, smc, tid);
            ZACC();
            mma_pass(CURS(pb + 1) + aoffB, sb + XHB + boffB, 8, acc);
            {
                const float wtA = smf[WTf + l * 384 + 128 + og],  wtB = smf[WTf + l * 384 + 128 + og8];
                const float bzA = smf[FBf + l * 512 + 128 + og],  bzB = smf[FBf + l * 512 + 128 + og8];
#pragma unroll
                for (int j = 0; j < 2; j++) {
                    const int b0 = 8 * (2 * nh + j) + 2 * tg;
                    const float tv0 = smf[TVf + b0], tv1 = smf[TVf + b0 + 1];
                    zf[4 * j + 0] = 0.4f * siga(acc[4 * j + 0] + wtA * tv0 + bzA);
                    zf[4 * j + 1] = 0.4f * siga(acc[4 * j + 1] + wtA * tv1 + bzA);
                    zf[4 * j + 2] = 0.4f * siga(acc[4 * j + 2] + wtB * tv0 + bzB);
                    zf[4 * j + 3] = 0.4f * siga(acc[4 * j + 3] + wtB * tv1 + bzB);
                }
            }

            // ---- pass u + combine ----
            phsync(pb + 2, smc, tid);
            ZACC();
            mma_pass(CURS(pb + 2) + aoffB, sb + XRB + boffB, 8, acc);
            {
                const float wtA = smf[WTf + l * 384 + 256 + og],  wtB = smf[WTf + l * 384 + 256 + og8];
                const float bhA = smf[FBf + l * 512 + 256 + og],  bhB = smf[FBf + l * 512 + 256 + og8];
                const float twA = smf[FBf + l * 512 + 384 + og],  twB = smf[FBf + l * 512 + 384 + og8];
#define FLOWU(jj, bb, oo, wt, bh, tw, tvv) do { \
                    const float u_ = tanha(acc[jj] + (wt) * (tvv) + (bh)); \
                    const float phi_ = tanha((tw) * (tvv)); \
                    const float h_ = smf[HMf + (bb) * 132 + (oo)]; \
                    const float hn_ = h_ + phi_ * zf[jj] * (u_ - h_); \
                    smf[HMf + (bb) * 132 + (oo)] = hn_; \
                    st_h(smc, XHB, (bb), (oo), hn_); \
                    if (l == 1) hids[((size_t)(row0 + (bb)) * T_STEPS + ti) * 128 + (oo)] = hn_; \
                } while (0)
#pragma unroll
                for (int j = 0; j < 2; j++) {
                    const int b0 = 8 * (2 * nh + j) + 2 * tg;
                    const float tv0 = smf[TVf + b0], tv1 = smf[TVf + b0 + 1];
                    FLOWU(4 * j + 0, b0,     og,  wtA, bhA, twA, tv0);
                    FLOWU(4 * j + 1, b0 + 1, og,  wtA, bhA, twA, tv1);
                    FLOWU(4 * j + 2, b0,     og8, wtB, bhB, twB, tv0);
                    FLOWU(4 * j + 3, b0 + 1, og8, wtB, bhB, twB, tv1);
                }
#undef FLOWU
            }
        }

        // =================== GRU ===================
        // r gate: gh_r then += gi_r
        phsync(6, smc, tid);
        ZACC();
        mma_pass(CURS(6) + aoffB, sb + XHB + boffB, 8, acc);
        phsync(7, smc, tid);
        mma_pass(CURS(7) + aoffG, sb + XGB + boffG, 3, acc);
        {
            const float bA = smf[GBf + og], bB = smf[GBf + og8];
#pragma unroll
            for (int j = 0; j < 2; j++) {
                rv[4 * j + 0] = siga(acc[4 * j + 0] + bA);
                rv[4 * j + 1] = siga(acc[4 * j + 1] + bA);
                rv[4 * j + 2] = siga(acc[4 * j + 2] + bB);
                rv[4 * j + 3] = siga(acc[4 * j + 3] + bB);
            }
        }
        // z gate
        phsync(8, smc, tid);
        ZACC();
        mma_pass(CURS(8) + aoffB, sb + XHB + boffB, 8, acc);
        phsync(9, smc, tid);
        mma_pass(CURS(9) + aoffG, sb + XGB + boffG, 3, acc);
        {
            const float bA = smf[GBf + 128 + og], bB = smf[GBf + 128 + og8];
#pragma unroll
            for (int j = 0; j < 2; j++) {
                zf[4 * j + 0] = siga(acc[4 * j + 0] + bA);
                zf[4 * j + 1] = siga(acc[4 * j + 1] + bA);
                zf[4 * j + 2] = siga(acc[4 * j + 2] + bB);
                zf[4 * j + 3] = siga(acc[4 * j + 3] + bB);
            }
        }
        // gh_n -> fold into rv
        phsync(10, smc, tid);
        ZACC();
        mma_pass(CURS(10) + aoffB, sb + XHB + boffB, 8, acc);
        {
            const float bA = smf[GBf + 384 + og], bB = smf[GBf + 384 + og8];
#pragma unroll
            for (int j = 0; j < 2; j++) {
                rv[4 * j + 0] *= (acc[4 * j + 0] + bA);
                rv[4 * j + 1] *= (acc[4 * j + 1] + bA);
                rv[4 * j + 2] *= (acc[4 * j + 2] + bB);
                rv[4 * j + 3] *= (acc[4 * j + 3] + bB);
            }
        }
        // gi_n + combine
        phsync(11, smc, tid);
        ZACC();
        mma_pass(CURS(11) + aoffG, sb + XGB + boffG, 3, acc);
        {
            const float bA = smf[GBf + 256 + og], bB = smf[GBf + 256 + og8];
#define GRUF(jj, bb, oo, bi) do { \
                const float nn_ = tanha(acc[jj] + (bi) + rv[jj]); \
                const float h_ = smf[HMf + (bb) * 132 + (oo)]; \
                const float hn_ = nn_ + zf[jj] * (h_ - nn_); \
                smf[HMf + (bb) * 132 + (oo)] = hn_; \
                st_h(smc, XHB, (bb), (oo), hn_); \
            } while (0)
#pragma unroll
            for (int j = 0; j < 2; j++) {
                const int b0 = 8 * (2 * nh + j) + 2 * tg;
                GRUF(4 * j + 0, b0,     og,  bA);
                GRUF(4 * j + 1, b0 + 1, og,  bA);
                GRUF(4 * j + 2, b0,     og8, bB);
                GRUF(4 * j + 3, b0 + 1, og8, bB);
            }
#undef GRUF
        }
        __syncthreads();   // HM complete for decoder

        // =================== decoder (fp32) ===================
        {
            const int d = lane;
            const int bq = w * 2;
            float o0, o1;
            o0 = o1 = smf[DBf + d];
#pragma unroll 2
            for (int k = 0; k < 128; k += 4) {
                const float w0 = smf[DECf + (k + 0) * 33 + d];
                const float w1 = smf[DECf + (k + 1) * 33 + d];
                const float w2 = smf[DECf + (k + 2) * 33 + d];
                const float w3 = smf[DECf + (k + 3) * 33 + d];
                float4 h0 = *(const float4*)&smf[HMf + (bq + 0) * 132 + k];
                float4 h1 = *(const float4*)&smf[HMf + (bq + 1) * 132 + k];
                o0 = fmaf(h0.x, w0, fmaf(h0.y, w1, fmaf(h0.z, w2, fmaf(h0.w, w3, o0))));
                o1 = fmaf(h1.x, w0, fmaf(h1.y, w1, fmaf(h1.z, w2, fmaf(h1.w, w3, o1))));
            }
            outs[((size_t)(row0 + bq + 0) * T_STEPS + ti) * 32 + d] = o0;
            outs[((size_t)(row0 + bq + 1) * T_STEPS + ti) * 32 + d] = o1;
        }
    }
}

extern "C" void kernel_launch(void* const* d_in, const int* in_sizes, int n_in,
                              void* d_out, int out_size)
{
    (void)in_sizes; (void)n_in; (void)out_size;
    const float* s    = (const float*)d_in[0];
    const float* a    = (const float*)d_in[1];
    const float* t    = (const float*)d_in[2];
    const float* fWr  = (const float*)d_in[3];
    const float* fbr  = (const float*)d_in[4];
    const float* fWz  = (const float*)d_in[5];
    const float* fbz  = (const float*)d_in[6];
    const float* fWh  = (const float*)d_in[7];
    const float* fbh  = (const float*)d_in[8];
    const float* ftw  = (const float*)d_in[9];
    const float* Wih  = (const float*)d_in[10];
    const float* Whh  = (const float*)d_in[11];
    const float* bih  = (const float*)d_in[12];
    const float* bhh  = (const float*)d_in[13];
    const float* decW = (const float*)d_in[14];
    const float* decb = (const float*)d_in[15];

    float* outs = (float*)d_out;
    float* hids = outs + (size_t)4096 * T_STEPS * 32;

    prep_kernel<<<12, 256>>>(fWr, fWz, fWh, Whh, Wih);

    cudaFuncSetAttribute(odernn_mma, cudaFuncAttributeMaxDynamicSharedMemorySize, SMEM_BYTES);
    odernn_mma<<<128, NTHR, SMEM_BYTES>>>(s, a, t, fWr, fbr, fWz, fbz, fWh, fbh, ftw,
                                          bih, bhh, decW, decb, outs, hids);
}

// round 15
// speedup vs baseline: 1.8325x; 1.2227x over previous
#include <cuda_runtime.h>
#include <cuda_fp16.h>
#include <stdint.h>
#include <stddef.h>

#define T_STEPS 200
#define NTHR 512

// ---------------- smem layout ----------------
// bytes:
#define XHB    0          // h   B-tile [32][136] fp16 (8704 B)
#define XRB    8704       // r*h B-tile (8704 B)
#define XGB    17408      // gru x B-tile [32][56] fp16 (3584 B)
// float offsets:
#define HMf    5248       // h fp32 master [32][132]  (4224 f)
#define DECf   9472       // dec weights [k=128][33]  (4224 f)
#define FBf    13696      // flow biases [l*512 + gate*128 + n] (1024 f)
#define WTf    14720      // flow t-row weights [l*384 + gate*128 + n] (768 f)
#define GBf    15488      // gru biases: br,bz,bin,bhn (512 f)
#define DBf    16000      // dec bias (32 f)
#define TVf    16032      // t values (32 f)
#define SMEM_BYTES 64256

// fp16 weight images, fragment-linear layout (built once per launch by prep_kernel)
// big imgs 0..8 (M=128,K=128): 16384 shorts each; small imgs 9..11 (M=128,K=48): 6144 shorts
__device__ __align__(16) unsigned short g_wimg[165888];

__device__ __forceinline__ float tanha(float x) {
    float y; asm("tanh.approx.f32 %0,%1;" : "=f"(y) : "f"(x)); return y;
}
__device__ __forceinline__ float siga(float x) { return fmaf(0.5f, tanha(0.5f * x), 0.5f); }

__device__ __forceinline__ void ldm4(uint32_t& r0, uint32_t& r1, uint32_t& r2, uint32_t& r3, uint32_t a) {
    asm volatile("ldmatrix.sync.aligned.m8n8.x4.shared.b16 {%0,%1,%2,%3},[%4];"
        : "=r"(r0), "=r"(r1), "=r"(r2), "=r"(r3) : "r"(a));
}
__device__ __forceinline__ void mmaf16(float* d, uint32_t a0, uint32_t a1, uint32_t a2, uint32_t a3,
                                       uint32_t b0, uint32_t b1) {
    asm volatile("mma.sync.aligned.m16n8k16.row.col.f32.f16.f16.f32 "
        "{%0,%1,%2,%3},{%4,%5,%6,%7},{%8,%9},{%0,%1,%2,%3};"
        : "+f"(d[0]), "+f"(d[1]), "+f"(d[2]), "+f"(d[3])
        : "r"(a0), "r"(a1), "r"(a2), "r"(a3), "r"(b0), "r"(b1));
}

// fp16 B-tile store helpers
__device__ __forceinline__ void st_h(char* smc, int baseB, int b, int k, float v) {
    *(__half*)(smc + baseB + (b * 136 + k) * 2) = __float2half(v);
}
__device__ __forceinline__ void st_h56(char* smc, int baseB, int b, int k, float v) {
    *(__half*)(smc + baseB + (b * 56 + k) * 2) = __float2half(v);
}

// one matvec pass: A fragments direct from gmem (LDG.128/lane/kstep), B via ldmatrix.
// Aw = warp's fragment stream base (pre-offset by img, m-tile, lane); frag ks at Aw[ks*32].
template<int KS>
__device__ __forceinline__ void mma_pass(const uint4* __restrict__ Aw, uint32_t Baddr, float acc[8])
{
#pragma unroll
    for (int ks = 0; ks < KS; ks++) {
        const uint4 fa = __ldg(Aw + ks * 32);
        uint32_t b0, b1, b2, b3;
        ldm4(b0, b1, b2, b3, Baddr + ks * 32);
        mmaf16(acc + 0, fa.x, fa.y, fa.z, fa.w, b0, b1);
        mmaf16(acc + 4, fa.x, fa.y, fa.z, fa.w, b2, b3);
    }
}

// -------------------- prep: build fragment-linear fp16 weight images --------------------
// imgs 0..5 flow (Wr0,Wz0,Wh0,Wr1,Wz1,Wh1): A(n,k)=W[k*128+n], K=128
// imgs 6..8 Whh gates:                      A(n,k)=Whh[g][n*128+k], K=128
// imgs 9..11 Wih gates:                     A(n,k)=Wih[(g*128+n)*40+k] (k<40 else 0), K=48
__global__ void prep_kernel(const float* fWr, const float* fWz, const float* fWh,
                            const float* Whh, const float* Wih)
{
    const int img = blockIdx.x, tid = threadIdx.x;
    const int KS = (img < 9) ? 8 : 3;
    unsigned short* dst = (img < 9) ? (g_wimg + img * 16384)
                                    : (g_wimg + 147456 + (img - 9) * 6144);
    const int nfrag = 8 * KS * 32;
    for (int idx = tid; idx < nfrag; idx += 256) {
        const int mt   = idx / (KS * 32);
        const int rem  = idx - mt * (KS * 32);
        const int ks   = rem >> 5;
        const int lane = rem & 31;
        const int R = 16 * mt + (lane >> 2);
        const int C = 16 * ks + (lane & 3) * 2;
        float v[8];
#pragma unroll
        for (int q = 0; q < 8; q++) {
            const int r = R + ((q >> 1) & 1) * 8;        // q=0,1:+0  q=2,3:+8  q=4,5:+0 q=6,7:+8
            const int c = C + (q >> 2) * 8 + (q & 1);
            float val = 0.0f;
            if (img < 6) {
                const int l = img / 3, g = img % 3;
                const float* W = (g == 0 ? fWr : (g == 1 ? fWz : fWh)) + (size_t)l * 129 * 128;
                val = W[c * 128 + r];
            } else if (img < 9) {
                val = Whh[(size_t)(img - 6) * 16384 + r * 128 + c];
            } else {
                if (c < 40) val = Wih[(size_t)((img - 9) * 128 + r) * 40 + c];
            }
            v[q] = val;
        }
        unsigned short* o = dst + idx * 8;
#pragma unroll
        for (int q = 0; q < 8; q++) {
            __half h = __float2half(v[q]);
            o[q] = *reinterpret_cast<unsigned short*>(&h);
        }
    }
}

#define ZACC() do { _Pragma("unroll") for (int q = 0; q < 8; q++) acc[q] = 0.0f; } while (0)
// warp A-stream base for big / small images (uint4 units)
#define AW_BIG(i)   (W4 + (i) * 2048 + mw * 256 + lane)
#define AW_SML(g)   (W4 + 18432 + (g) * 768 + mw * 96 + lane)

__global__ void __launch_bounds__(NTHR, 1)
odernn_mma(const float* __restrict__ s, const float* __restrict__ a, const float* __restrict__ t,
           const float* __restrict__ fWr, const float* __restrict__ fbr,
           const float* __restrict__ fWz, const float* __restrict__ fbz,
           const float* __restrict__ fWh, const float* __restrict__ fbh,
           const float* __restrict__ ftw,
           const float* __restrict__ bih, const float* __restrict__ bhh,
           const float* __restrict__ decW, const float* __restrict__ decb,
           float* __restrict__ outs, float* __restrict__ hids)
{
    extern __shared__ char smc[];
    float* smf = (float*)smc;
    const int tid = threadIdx.x;
    const int row0 = blockIdx.x * 32;
    const uint32_t sb = (uint32_t)__cvta_generic_to_shared(smc);
    const uint4* W4 = reinterpret_cast<const uint4*>(g_wimg);

    const int w = tid >> 5, lane = tid & 31;
    const int mw = w & 7, nh = w >> 3;       // m-tile 0..7, n-half 0..1
    const int g = lane >> 2, tg = lane & 3;
    const int og = 16 * mw + g, og8 = og + 8;
    // B ldmatrix x4 covering two n-tiles (rows 16nh..16nh+15), k16
    const int brow = 16 * nh + (lane & 7) + ((lane >> 4) & 1) * 8;
    const uint32_t boffB = (uint32_t)(brow * 272 + ((lane >> 3) & 1) * 16);
    const uint32_t boffG = (uint32_t)(brow * 112 + ((lane >> 3) & 1) * 16);

    // ---- one-time init ----
    for (int i = tid; i < 5248; i += NTHR) smf[i] = 0.0f;            // XH/XR/XG zero
    for (int i = tid; i < 4224; i += NTHR) smf[HMf + i] = 0.0f;      // h master zero
    for (int i = tid; i < 4096; i += NTHR) {                          // dec [k][33]
        const int d = i >> 7, k = i & 127;
        smf[DECf + k * 33 + d] = decW[i];
    }
    if (tid < 128) {
#pragma unroll
        for (int l = 0; l < 2; l++) {
            smf[FBf + l * 512 +   0 + tid] = fbr[l * 128 + tid];
            smf[FBf + l * 512 + 128 + tid] = fbz[l * 128 + tid];
            smf[FBf + l * 512 + 256 + tid] = fbh[l * 128 + tid];
            smf[FBf + l * 512 + 384 + tid] = ftw[l * 128 + tid];
            smf[WTf + l * 384 +   0 + tid] = fWr[l * 16512 + 16384 + tid];
            smf[WTf + l * 384 + 128 + tid] = fWz[l * 16512 + 16384 + tid];
            smf[WTf + l * 384 + 256 + tid] = fWh[l * 16512 + 16384 + tid];
        }
        smf[GBf +   0 + tid] = bih[tid] + bhh[tid];
        smf[GBf + 128 + tid] = bih[128 + tid] + bhh[128 + tid];
        smf[GBf + 256 + tid] = bih[256 + tid];
        smf[GBf + 384 + tid] = bhh[256 + tid];
    }
    if (tid < 32) smf[DBf + tid] = decb[tid];
    __syncthreads();

#pragma unroll 1
    for (int ti = 0; ti < T_STEPS; ti++) {
        if (tid < 32) smf[TVf + tid] = t[(size_t)(row0 + tid) * T_STEPS + ti];
        for (int i = tid; i < 1280; i += NTHR) {
            const int b = i / 40, c = i - b * 40;
            const float v = (c < 32) ? s[((size_t)(row0 + b) * T_STEPS + ti) * 32 + c]
                                     : a[((size_t)(row0 + b) * T_STEPS + ti) * 8 + (c - 32)];
            st_h56(smc, XGB, b, c, v);
        }

        float acc[8], zf[8], rv[8];

        // =================== flow layers ===================
#pragma unroll 1
        for (int l = 0; l < 2; l++) {
            // ---- pass r ----
            __syncthreads();
            ZACC();
            mma_pass<8>(AW_BIG(l * 3 + 0), sb + XHB + boffB, acc);
            {
                const float wtA = smf[WTf + l * 384 + og],  wtB = smf[WTf + l * 384 + og8];
                const float brA = smf[FBf + l * 512 + og],  brB = smf[FBf + l * 512 + og8];
#pragma unroll
                for (int j = 0; j < 2; j++) {
                    const int b0 = 8 * (2 * nh + j) + 2 * tg;
                    const float tv0 = smf[TVf + b0], tv1 = smf[TVf + b0 + 1];
                    float r0 = 0.8f * siga(acc[4 * j + 0] + wtA * tv0 + brA);
                    float r1 = 0.8f * siga(acc[4 * j + 1] + wtA * tv1 + brA);
                    float r2 = 0.8f * siga(acc[4 * j + 2] + wtB * tv0 + brB);
                    float r3 = 0.8f * siga(acc[4 * j + 3] + wtB * tv1 + brB);
                    st_h(smc, XRB, b0,     og,  r0 * smf[HMf + b0 * 132 + og]);
                    st_h(smc, XRB, b0 + 1, og,  r1 * smf[HMf + (b0 + 1) * 132 + og]);
                    st_h(smc, XRB, b0,     og8, r2 * smf[HMf + b0 * 132 + og8]);
                    st_h(smc, XRB, b0 + 1, og8, r3 * smf[HMf + (b0 + 1) * 132 + og8]);
                }
            }

            // ---- pass z ----
            __syncthreads();
            ZACC();
            mma_pass<8>(AW_BIG(l * 3 + 1), sb + XHB + boffB, acc);
            {
                const float wtA = smf[WTf + l * 384 + 128 + og],  wtB = smf[WTf + l * 384 + 128 + og8];
                const float bzA = smf[FBf + l * 512 + 128 + og],  bzB = smf[FBf + l * 512 + 128 + og8];
#pragma unroll
                for (int j = 0; j < 2; j++) {
                    const int b0 = 8 * (2 * nh + j) + 2 * tg;
                    const float tv0 = smf[TVf + b0], tv1 = smf[TVf + b0 + 1];
                    zf[4 * j + 0] = 0.4f * siga(acc[4 * j + 0] + wtA * tv0 + bzA);
                    zf[4 * j + 1] = 0.4f * siga(acc[4 * j + 1] + wtA * tv1 + bzA);
                    zf[4 * j + 2] = 0.4f * siga(acc[4 * j + 2] + wtB * tv0 + bzB);
                    zf[4 * j + 3] = 0.4f * siga(acc[4 * j + 3] + wtB * tv1 + bzB);
                }
            }

            // ---- pass u + combine ----
            __syncthreads();
            ZACC();
            mma_pass<8>(AW_BIG(l * 3 + 2), sb + XRB + boffB, acc);
            {
                const float wtA = smf[WTf + l * 384 + 256 + og],  wtB = smf[WTf + l * 384 + 256 + og8];
                const float bhA = smf[FBf + l * 512 + 256 + og],  bhB = smf[FBf + l * 512 + 256 + og8];
                const float twA = smf[FBf + l * 512 + 384 + og],  twB = smf[FBf + l * 512 + 384 + og8];
#define FLOWU(jj, bb, oo, wt, bh, tw, tvv) do { \
                    const float u_ = tanha(acc[jj] + (wt) * (tvv) + (bh)); \
                    const float phi_ = tanha((tw) * (tvv)); \
                    const float h_ = smf[HMf + (bb) * 132 + (oo)]; \
                    const float hn_ = h_ + phi_ * zf[jj] * (u_ - h_); \
                    smf[HMf + (bb) * 132 + (oo)] = hn_; \
                    st_h(smc, XHB, (bb), (oo), hn_); \
                    if (l == 1) hids[((size_t)(row0 + (bb)) * T_STEPS + ti) * 128 + (oo)] = hn_; \
                } while (0)
#pragma unroll
                for (int j = 0; j < 2; j++) {
                    const int b0 = 8 * (2 * nh + j) + 2 * tg;
                    const float tv0 = smf[TVf + b0], tv1 = smf[TVf + b0 + 1];
                    FLOWU(4 * j + 0, b0,     og,  wtA, bhA, twA, tv0);
                    FLOWU(4 * j + 1, b0 + 1, og,  wtA, bhA, twA, tv1);
                    FLOWU(4 * j + 2, b0,     og8, wtB, bhB, twB, tv0);
                    FLOWU(4 * j + 3, b0 + 1, og8, wtB, bhB, twB, tv1);
                }
#undef FLOWU
            }
        }

        // =================== GRU ===================
        // r gate: gh_r then += gi_r
        __syncthreads();
        ZACC();
        mma_pass<8>(AW_BIG(6), sb + XHB + boffB, acc);
        mma_pass<3>(AW_SML(0), sb + XGB + boffG, acc);
        {
            const float bA = smf[GBf + og], bB = smf[GBf + og8];
#pragma unroll
            for (int j = 0; j < 2; j++) {
                rv[4 * j + 0] = siga(acc[4 * j + 0] + bA);
                rv[4 * j + 1] = siga(acc[4 * j + 1] + bA);
                rv[4 * j + 2] = siga(acc[4 * j + 2] + bB);
                rv[4 * j + 3] = siga(acc[4 * j + 3] + bB);
            }
        }
        // z gate
        ZACC();
        mma_pass<8>(AW_BIG(7), sb + XHB + boffB, acc);
        mma_pass<3>(AW_SML(1), sb + XGB + boffG, acc);
        {
            const float bA = smf[GBf + 128 + og], bB = smf[GBf + 128 + og8];
#pragma unroll
            for (int j = 0; j < 2; j++) {
                zf[4 * j + 0] = siga(acc[4 * j + 0] + bA);
                zf[4 * j + 1] = siga(acc[4 * j + 1] + bA);
                zf[4 * j + 2] = siga(acc[4 * j + 2] + bB);
                zf[4 * j + 3] = siga(acc[4 * j + 3] + bB);
            }
        }
        // gh_n -> fold into rv
        ZACC();
        mma_pass<8>(AW_BIG(8), sb + XHB + boffB, acc);
        {
            const float bA = smf[GBf + 384 + og], bB = smf[GBf + 384 + og8];
#pragma unroll
            for (int j = 0; j < 2; j++) {
                rv[4 * j + 0] *= (acc[4 * j + 0] + bA);
                rv[4 * j + 1] *= (acc[4 * j + 1] + bA);
                rv[4 * j + 2] *= (acc[4 * j + 2] + bB);
                rv[4 * j + 3] *= (acc[4 * j + 3] + bB);
            }
        }
        // gi_n + combine
        ZACC();
        mma_pass<3>(AW_SML(2), sb + XGB + boffG, acc);
        {
            const float bA = smf[GBf + 256 + og], bB = smf[GBf + 256 + og8];
#define GRUF(jj, bb, oo, bi) do { \
                const float nn_ = tanha(acc[jj] + (bi) + rv[jj]); \
                const float h_ = smf[HMf + (bb) * 132 + (oo)]; \
                const float hn_ = nn_ + zf[jj] * (h_ - nn_); \
                smf[HMf + (bb) * 132 + (oo)] = hn_; \
                st_h(smc, XHB, (bb), (oo), hn_); \
            } while (0)
#pragma unroll
            for (int j = 0; j < 2; j++) {
                const int b0 = 8 * (2 * nh + j) + 2 * tg;
                GRUF(4 * j + 0, b0,     og,  bA);
                GRUF(4 * j + 1, b0 + 1, og,  bA);
                GRUF(4 * j + 2, b0,     og8, bB);
                GRUF(4 * j + 3, b0 + 1, og8, bB);
            }
#undef GRUF
        }
        __syncthreads();   // HM complete for decoder; XH writes before next step reads

        // =================== decoder (fp32) ===================
        {
            const int d = lane;
            const int bq = w * 2;
            float o0, o1;
            o0 = o1 = smf[DBf + d];
#pragma unroll 2
            for (int k = 0; k < 128; k += 4) {
                const float w0 = smf[DECf + (k + 0) * 33 + d];
                const float w1 = smf[DECf + (k + 1) * 33 + d];
                const float w2 = smf[DECf + (k + 2) * 33 + d];
                const float w3 = smf[DECf + (k + 3) * 33 + d];
                float4 h0 = *(const float4*)&smf[HMf + (bq + 0) * 132 + k];
                float4 h1 = *(const float4*)&smf[HMf + (bq + 1) * 132 + k];
                o0 = fmaf(h0.x, w0, fmaf(h0.y, w1, fmaf(h0.z, w2, fmaf(h0.w, w3, o0))));
                o1 = fmaf(h1.x, w0, fmaf(h1.y, w1, fmaf(h1.z, w2, fmaf(h1.w, w3, o1))));
            }
            outs[((size_t)(row0 + bq + 0) * T_STEPS + ti) * 32 + d] = o0;
            outs[((size_t)(row0 + bq + 1) * T_STEPS + ti) * 32 + d] = o1;
        }
    }
}

extern "C" void kernel_launch(void* const* d_in, const int* in_sizes, int n_in,
                              void* d_out, int out_size)
{
    (void)in_sizes; (void)n_in; (void)out_size;
    const float* s    = (const float*)d_in[0];
    const float* a    = (const float*)d_in[1];
    const float* t    = (const float*)d_in[2];
    const float* fWr  = (const float*)d_in[3];
    const float* fbr  = (const float*)d_in[4];
    const float* fWz  = (const float*)d_in[5];
    const float* fbz  = (const float*)d_in[6];
    const float* fWh  = (const float*)d_in[7];
    const float* fbh  = (const float*)d_in[8];
    const float* ftw  = (const float*)d_in[9];
    const float* Wih  = (const float*)d_in[10];
    const float* Whh  = (const float*)d_in[11];
    const float* bih  = (const float*)d_in[12];
    const float* bhh  = (const float*)d_in[13];
    const float* decW = (const float*)d_in[14];
    const float* decb = (const float*)d_in[15];

    float* outs = (float*)d_out;
    float* hids = outs + (size_t)4096 * T_STEPS * 32;

    prep_kernel<<<12, 256>>>(fWr, fWz, fWh, Whh, Wih);

    cudaFuncSetAttribute(odernn_mma, cudaFuncAttributeMaxDynamicSharedMemorySize, SMEM_BYTES);
    odernn_mma<<<128, NTHR, SMEM_BYTES>>>(s, a, t, fWr, fbr, fWz, fbz, fWh, fbh, ftw,
                                          bih, bhh, decW, decb, outs, hids);
}

// round 16
// speedup vs baseline: 1.9956x; 1.0890x over previous
#include <cuda_runtime.h>
#include <cuda_fp16.h>
#include <stdint.h>
#include <stddef.h>

#define T_STEPS 200
#define NTHR 256
#define ROWS 16

// ---------------- smem layout ----------------
// bytes:
#define XHB    0          // h   B-tile [16][136] fp16 (4352 B)
#define XRB    4352       // r*h B-tile (4352 B)
#define XGB    8704       // gru x B-tile [16][56] fp16 (1792 B)
// float offsets:
#define HMf    2624       // h fp32 master [16][132]  (2112 f)
#define DECf   4736       // dec weights [k=128][33]  (4224 f)
#define FBf    8960       // flow biases [l*512 + gate*128 + n] (1024 f)
#define WTf    9984       // flow t-row weights [l*384 + gate*128 + n] (768 f)
#define GBf    10752      // gru biases: br,bz,bin,bhn (512 f)
#define DBf    11264      // dec bias (32 f)
#define TVf    11296      // t values (16 f)
#define SMEM_BYTES 45248

// fp16 weight images, fragment-linear layout (built once per launch by prep_kernel)
// big imgs 0..8 (M=128,K=128): 16384 shorts each; small imgs 9..11 (M=128,K=48): 6144 shorts
__device__ __align__(16) unsigned short g_wimg[165888];

__device__ __forceinline__ float tanha(float x) {
    float y; asm("tanh.approx.f32 %0,%1;" : "=f"(y) : "f"(x)); return y;
}
__device__ __forceinline__ float siga(float x) { return fmaf(0.5f, tanha(0.5f * x), 0.5f); }

__device__ __forceinline__ void ldm4(uint32_t& r0, uint32_t& r1, uint32_t& r2, uint32_t& r3, uint32_t a) {
    asm volatile("ldmatrix.sync.aligned.m8n8.x4.shared.b16 {%0,%1,%2,%3},[%4];"
        : "=r"(r0), "=r"(r1), "=r"(r2), "=r"(r3) : "r"(a));
}
__device__ __forceinline__ void mmaf16(float* d, uint32_t a0, uint32_t a1, uint32_t a2, uint32_t a3,
                                       uint32_t b0, uint32_t b1) {
    asm volatile("mma.sync.aligned.m16n8k16.row.col.f32.f16.f16.f32 "
        "{%0,%1,%2,%3},{%4,%5,%6,%7},{%8,%9},{%0,%1,%2,%3};"
        : "+f"(d[0]), "+f"(d[1]), "+f"(d[2]), "+f"(d[3])
        : "r"(a0), "r"(a1), "r"(a2), "r"(a3), "r"(b0), "r"(b1));
}

// fp16 B-tile store helpers
__device__ __forceinline__ void st_h(char* smc, int baseB, int b, int k, float v) {
    *(__half*)(smc + baseB + (b * 136 + k) * 2) = __float2half(v);
}
__device__ __forceinline__ void st_h56(char* smc, int baseB, int b, int k, float v) {
    *(__half*)(smc + baseB + (b * 56 + k) * 2) = __float2half(v);
}

// one matvec pass: A fragments direct from gmem (LDG.128/lane/kstep), B via ldmatrix.
template<int KS>
__device__ __forceinline__ void mma_pass(const uint4* __restrict__ Aw, uint32_t Baddr, float acc[8])
{
#pragma unroll
    for (int ks = 0; ks < KS; ks++) {
        const uint4 fa = __ldg(Aw + ks * 32);
        uint32_t b0, b1, b2, b3;
        ldm4(b0, b1, b2, b3, Baddr + ks * 32);
        mmaf16(acc + 0, fa.x, fa.y, fa.z, fa.w, b0, b1);
        mmaf16(acc + 4, fa.x, fa.y, fa.z, fa.w, b2, b3);
    }
}

// -------------------- prep: build fragment-linear fp16 weight images --------------------
__global__ void prep_kernel(const float* fWr, const float* fWz, const float* fWh,
                            const float* Whh, const float* Wih)
{
    const int img = blockIdx.x, tid = threadIdx.x;
    const int KS = (img < 9) ? 8 : 3;
    unsigned short* dst = (img < 9) ? (g_wimg + img * 16384)
                                    : (g_wimg + 147456 + (img - 9) * 6144);
    const int nfrag = 8 * KS * 32;
    for (int idx = tid; idx < nfrag; idx += 256) {
        const int mt   = idx / (KS * 32);
        const int rem  = idx - mt * (KS * 32);
        const int ks   = rem >> 5;
        const int lane = rem & 31;
        const int R = 16 * mt + (lane >> 2);
        const int C = 16 * ks + (lane & 3) * 2;
        float v[8];
#pragma unroll
        for (int q = 0; q < 8; q++) {
            const int r = R + ((q >> 1) & 1) * 8;
            const int c = C + (q >> 2) * 8 + (q & 1);
            float val = 0.0f;
            if (img < 6) {
                const int l = img / 3, g = img % 3;
                const float* W = (g == 0 ? fWr : (g == 1 ? fWz : fWh)) + (size_t)l * 129 * 128;
                val = W[c * 128 + r];
            } else if (img < 9) {
                val = Whh[(size_t)(img - 6) * 16384 + r * 128 + c];
            } else {
                if (c < 40) val = Wih[(size_t)((img - 9) * 128 + r) * 40 + c];
            }
            v[q] = val;
        }
        unsigned short* o = dst + idx * 8;
#pragma unroll
        for (int q = 0; q < 8; q++) {
            __half h = __float2half(v[q]);
            o[q] = *reinterpret_cast<unsigned short*>(&h);
        }
    }
}

#define ZACC() do { _Pragma("unroll") for (int q = 0; q < 8; q++) acc[q] = 0.0f; } while (0)
#define AW_BIG(i)   (W4 + (i) * 2048 + mw * 256 + lane)
#define AW_SML(g)   (W4 + 18432 + (g) * 768 + mw * 96 + lane)

__global__ void __launch_bounds__(NTHR, 2)
odernn_mma(const float* __restrict__ s, const float* __restrict__ a, const float* __restrict__ t,
           const float* __restrict__ fWr, const float* __restrict__ fbr,
           const float* __restrict__ fWz, const float* __restrict__ fbz,
           const float* __restrict__ fWh, const float* __restrict__ fbh,
           const float* __restrict__ ftw,
           const float* __restrict__ bih, const float* __restrict__ bhh,
           const float* __restrict__ decW, const float* __restrict__ decb,
           float* __restrict__ outs, float* __restrict__ hids)
{
    extern __shared__ char smc[];
    float* smf = (float*)smc;
    const int tid = threadIdx.x;
    const int row0 = blockIdx.x * ROWS;
    const uint32_t sb = (uint32_t)__cvta_generic_to_shared(smc);
    const uint4* W4 = reinterpret_cast<const uint4*>(g_wimg);

    const int w = tid >> 5, lane = tid & 31;
    const int mw = w;                         // m-tile 0..7
    const int g = lane >> 2, tg = lane & 3;
    const int og = 16 * mw + g, og8 = og + 8;
    // B ldmatrix x4 covering two n-tiles (rows 0..15), k16
    const int brow = (lane & 7) + ((lane >> 4) & 1) * 8;
    const uint32_t boffB = (uint32_t)(brow * 272 + ((lane >> 3) & 1) * 16);
    const uint32_t boffG = (uint32_t)(brow * 112 + ((lane >> 3) & 1) * 16);

    // ---- one-time init ----
    for (int i = tid; i < 2624; i += NTHR) smf[i] = 0.0f;            // XH/XR/XG zero
    for (int i = tid; i < 2112; i += NTHR) smf[HMf + i] = 0.0f;      // h master zero
    for (int i = tid; i < 4096; i += NTHR) {                          // dec [k][33]
        const int d = i >> 7, k = i & 127;
        smf[DECf + k * 33 + d] = decW[i];
    }
    if (tid < 128) {
#pragma unroll
        for (int l = 0; l < 2; l++) {
            smf[FBf + l * 512 +   0 + tid] = fbr[l * 128 + tid];
            smf[FBf + l * 512 + 128 + tid] = fbz[l * 128 + tid];
            smf[FBf + l * 512 + 256 + tid] = fbh[l * 128 + tid];
            smf[FBf + l * 512 + 384 + tid] = ftw[l * 128 + tid];
            smf[WTf + l * 384 +   0 + tid] = fWr[l * 16512 + 16384 + tid];
            smf[WTf + l * 384 + 128 + tid] = fWz[l * 16512 + 16384 + tid];
            smf[WTf + l * 384 + 256 + tid] = fWh[l * 16512 + 16384 + tid];
        }
        smf[GBf +   0 + tid] = bih[tid] + bhh[tid];
        smf[GBf + 128 + tid] = bih[128 + tid] + bhh[128 + tid];
        smf[GBf + 256 + tid] = bih[256 + tid];
        smf[GBf + 384 + tid] = bhh[256 + tid];
    }
    if (tid < 32) smf[DBf + tid] = decb[tid];
    __syncthreads();

#pragma unroll 1
    for (int ti = 0; ti < T_STEPS; ti++) {
        if (tid < ROWS) smf[TVf + tid] = t[(size_t)(row0 + tid) * T_STEPS + ti];
        for (int i = tid; i < ROWS * 40; i += NTHR) {
            const int b = i / 40, c = i - b * 40;
            const float v = (c < 32) ? s[((size_t)(row0 + b) * T_STEPS + ti) * 32 + c]
                                     : a[((size_t)(row0 + b) * T_STEPS + ti) * 8 + (c - 32)];
            st_h56(smc, XGB, b, c, v);
        }

        float acc[8], zf[8], rv[8];

        // =================== flow layers ===================
#pragma unroll 1
        for (int l = 0; l < 2; l++) {
            // ---- pass r ----
            __syncthreads();
            ZACC();
            mma_pass<8>(AW_BIG(l * 3 + 0), sb + XHB + boffB, acc);
            {
                const float wtA = smf[WTf + l * 384 + og],  wtB = smf[WTf + l * 384 + og8];
                const float brA = smf[FBf + l * 512 + og],  brB = smf[FBf + l * 512 + og8];
#pragma unroll
                for (int j = 0; j < 2; j++) {
                    const int b0 = 8 * j + 2 * tg;
                    const float tv0 = smf[TVf + b0], tv1 = smf[TVf + b0 + 1];
                    float r0 = 0.8f * siga(acc[4 * j + 0] + wtA * tv0 + brA);
                    float r1 = 0.8f * siga(acc[4 * j + 1] + wtA * tv1 + brA);
                    float r2 = 0.8f * siga(acc[4 * j + 2] + wtB * tv0 + brB);
                    float r3 = 0.8f * siga(acc[4 * j + 3] + wtB * tv1 + brB);
                    st_h(smc, XRB, b0,     og,  r0 * smf[HMf + b0 * 132 + og]);
                    st_h(smc, XRB, b0 + 1, og,  r1 * smf[HMf + (b0 + 1) * 132 + og]);
                    st_h(smc, XRB, b0,     og8, r2 * smf[HMf + b0 * 132 + og8]);
                    st_h(smc, XRB, b0 + 1, og8, r3 * smf[HMf + (b0 + 1) * 132 + og8]);
                }
            }

            // ---- pass z ----
            __syncthreads();
            ZACC();
            mma_pass<8>(AW_BIG(l * 3 + 1), sb + XHB + boffB, acc);
            {
                const float wtA = smf[WTf + l * 384 + 128 + og],  wtB = smf[WTf + l * 384 + 128 + og8];
                const float bzA = smf[FBf + l * 512 + 128 + og],  bzB = smf[FBf + l * 512 + 128 + og8];
#pragma unroll
                for (int j = 0; j < 2; j++) {
                    const int b0 = 8 * j + 2 * tg;
                    const float tv0 = smf[TVf + b0], tv1 = smf[TVf + b0 + 1];
                    zf[4 * j + 0] = 0.4f * siga(acc[4 * j + 0] + wtA * tv0 + bzA);
                    zf[4 * j + 1] = 0.4f * siga(acc[4 * j + 1] + wtA * tv1 + bzA);
                    zf[4 * j + 2] = 0.4f * siga(acc[4 * j + 2] + wtB * tv0 + bzB);
                    zf[4 * j + 3] = 0.4f * siga(acc[4 * j + 3] + wtB * tv1 + bzB);
                }
            }

            // ---- pass u + combine ----
            __syncthreads();
            ZACC();
            mma_pass<8>(AW_BIG(l * 3 + 2), sb + XRB + boffB, acc);
            {
                const float wtA = smf[WTf + l * 384 + 256 + og],  wtB = smf[WTf + l * 384 + 256 + og8];
                const float bhA = smf[FBf + l * 512 + 256 + og],  bhB = smf[FBf + l * 512 + 256 + og8];
                const float twA = smf[FBf + l * 512 + 384 + og],  twB = smf[FBf + l * 512 + 384 + og8];
#define FLOWU(jj, bb, oo, wt, bh, tw, tvv) do { \
                    const float u_ = tanha(acc[jj] + (wt) * (tvv) + (bh)); \
                    const float phi_ = tanha((tw) * (tvv)); \
                    const float h_ = smf[HMf + (bb) * 132 + (oo)]; \
                    const float hn_ = h_ + phi_ * zf[jj] * (u_ - h_); \
                    smf[HMf + (bb) * 132 + (oo)] = hn_; \
                    st_h(smc, XHB, (bb), (oo), hn_); \
                    if (l == 1) hids[((size_t)(row0 + (bb)) * T_STEPS + ti) * 128 + (oo)] = hn_; \
                } while (0)
#pragma unroll
                for (int j = 0; j < 2; j++) {
                    const int b0 = 8 * j + 2 * tg;
                    const float tv0 = smf[TVf + b0], tv1 = smf[TVf + b0 + 1];
                    FLOWU(4 * j + 0, b0,     og,  wtA, bhA, twA, tv0);
                    FLOWU(4 * j + 1, b0 + 1, og,  wtA, bhA, twA, tv1);
                    FLOWU(4 * j + 2, b0,     og8, wtB, bhB, twB, tv0);
                    FLOWU(4 * j + 3, b0 + 1, og8, wtB, bhB, twB, tv1);
                }
#undef FLOWU
            }
        }

        // =================== GRU ===================
        __syncthreads();
        // r gate: gh_r + gi_r
        ZACC();
        mma_pass<8>(AW_BIG(6), sb + XHB + boffB, acc);
        mma_pass<3>(AW_SML(0), sb + XGB + boffG, acc);
        {
            const float bA = smf[GBf + og], bB = smf[GBf + og8];
#pragma unroll
            for (int j = 0; j < 2; j++) {
                rv[4 * j + 0] = siga(acc[4 * j + 0] + bA);
                rv[4 * j + 1] = siga(acc[4 * j + 1] + bA);
                rv[4 * j + 2] = siga(acc[4 * j + 2] + bB);
                rv[4 * j + 3] = siga(acc[4 * j + 3] + bB);
            }
        }
        // z gate
        ZACC();
        mma_pass<8>(AW_BIG(7), sb + XHB + boffB, acc);
        mma_pass<3>(AW_SML(1), sb + XGB + boffG, acc);
        {
            const float bA = smf[GBf + 128 + og], bB = smf[GBf + 128 + og8];
#pragma unroll
            for (int j = 0; j < 2; j++) {
                zf[4 * j + 0] = siga(acc[4 * j + 0] + bA);
                zf[4 * j + 1] = siga(acc[4 * j + 1] + bA);
                zf[4 * j + 2] = siga(acc[4 * j + 2] + bB);
                zf[4 * j + 3] = siga(acc[4 * j + 3] + bB);
            }
        }
        // gh_n -> fold into rv
        ZACC();
        mma_pass<8>(AW_BIG(8), sb + XHB + boffB, acc);
        {
            const float bA = smf[GBf + 384 + og], bB = smf[GBf + 384 + og8];
#pragma unroll
            for (int j = 0; j < 2; j++) {
                rv[4 * j + 0] *= (acc[4 * j + 0] + bA);
                rv[4 * j + 1] *= (acc[4 * j + 1] + bA);
                rv[4 * j + 2] *= (acc[4 * j + 2] + bB);
                rv[4 * j + 3] *= (acc[4 * j + 3] + bB);
            }
        }
        // gi_n + combine
        ZACC();
        mma_pass<3>(AW_SML(2), sb + XGB + boffG, acc);
        {
            const float bA = smf[GBf + 256 + og], bB = smf[GBf + 256 + og8];
#define GRUF(jj, bb, oo, bi) do { \
                const float nn_ = tanha(acc[jj] + (bi) + rv[jj]); \
                const float h_ = smf[HMf + (bb) * 132 + (oo)]; \
                const float hn_ = nn_ + zf[jj] * (h_ - nn_); \
                smf[HMf + (bb) * 132 + (oo)] = hn_; \
                st_h(smc, XHB, (bb), (oo), hn_); \
            } while (0)
#pragma unroll
            for (int j = 0; j < 2; j++) {
                const int b0 = 8 * j + 2 * tg;
                GRUF(4 * j + 0, b0,     og,  bA);
                GRUF(4 * j + 1, b0 + 1, og,  bA);
                GRUF(4 * j + 2, b0,     og8, bB);
                GRUF(4 * j + 3, b0 + 1, og8, bB);
            }
#undef GRUF
        }
        __syncthreads();   // HM complete for decoder; XH/XG stable before next step writes

        // =================== decoder (fp32) ===================
        {
            const int d = lane;
            const int bq = w * 2;
            float o0, o1;
            o0 = o1 = smf[DBf + d];
#pragma unroll 2
            for (int k = 0; k < 128; k += 4) {
                const float w0 = smf[DECf + (k + 0) * 33 + d];
                const float w1 = smf[DECf + (k + 1) * 33 + d];
                const float w2 = smf[DECf + (k + 2) * 33 + d];
                const float w3 = smf[DECf + (k + 3) * 33 + d];
                float4 h0 = *(const float4*)&smf[HMf + (bq + 0) * 132 + k];
                float4 h1 = *(const float4*)&smf[HMf + (bq + 1) * 132 + k];
                o0 = fmaf(h0.x, w0, fmaf(h0.y, w1, fmaf(h0.z, w2, fmaf(h0.w, w3, o0))));
                o1 = fmaf(h1.x, w0, fmaf(h1.y, w1, fmaf(h1.z, w2, fmaf(h1.w, w3, o1))));
            }
            outs[((size_t)(row0 + bq + 0) * T_STEPS + ti) * 32 + d] = o0;
            outs[((size_t)(row0 + bq + 1) * T_STEPS + ti) * 32 + d] = o1;
        }
    }
}

extern "C" void kernel_launch(void* const* d_in, const int* in_sizes, int n_in,
                              void* d_out, int out_size)
{
    (void)in_sizes; (void)n_in; (void)out_size;
    const float* s    = (const float*)d_in[0];
    const float* a    = (const float*)d_in[1];
    const float* t    = (const float*)d_in[2];
    const float* fWr  = (const float*)d_in[3];
    const float* fbr  = (const float*)d_in[4];
    const float* fWz  = (const float*)d_in[5];
    const float* fbz  = (const float*)d_in[6];
    const float* fWh  = (const float*)d_in[7];
    const float* fbh  = (const float*)d_in[8];
    const float* ftw  = (const float*)d_in[9];
    const float* Wih  = (const float*)d_in[10];
    const float* Whh  = (const float*)d_in[11];
    const float* bih  = (const float*)d_in[12];
    const float* bhh  = (const float*)d_in[13];
    const float* decW = (const float*)d_in[14];
    const float* decb = (const float*)d_in[15];

    float* outs = (float*)d_out;
    float* hids = outs + (size_t)4096 * T_STEPS * 32;

    prep_kernel<<<12, 256>>>(fWr, fWz, fWh, Whh, Wih);

    cudaFuncSetAttribute(odernn_mma, cudaFuncAttributeMaxDynamicSharedMemorySize, SMEM_BYTES);
    odernn_mma<<<256, NTHR, SMEM_BYTES>>>(s, a, t, fWr, fbr, fWz, fbz, fWh, fbh, ftw,
                                          bih, bhh, decW, decb, outs, hids);
}